// round 14
// baseline (speedup 1.0000x reference)
#include <cuda_runtime.h>
#include <cuda_fp16.h>
#include <math.h>
#include <stdint.h>

#define B_ 2
#define S_ 2048
#define D_ 1024
#define L_ 6
#define H_ 16
#define HD_ 64
#define FF_ 4096
#define V_ 32000
#define TOK_ (B_ * S_)          // 4096 token rows

#define SCALE_LOG2 0.1803368801111f   // 0.125 * log2(e)

// ---------------- scratch (static device globals; no allocation) ----------
__device__ float g_x[TOK_ * D_];                 // fp32 residual stream
__device__ float g_tmp[TOK_ * FF_];              // out-proj / fc2 fp32 out
__device__ float g_o[TOK_ * D_];                 // fc2 out (pre-LN2)
__device__ __half g_xh[TOK_ * D_];               // x (fp16 plane)
__device__ __half g_oh[TOK_ * D_];               // attention out
__device__ __half g_hh[TOK_ * FF_];              // qkv / ffn hidden (fp16)
// preconverted fp16 weights, layout [K][N] per layer
__device__ __half g_wqkv[(size_t)L_ * D_ * 3 * D_];
__device__ __half g_wout[(size_t)L_ * D_ * D_];
__device__ __half g_wfc1[(size_t)L_ * D_ * FF_];
__device__ __half g_wfc2[(size_t)L_ * FF_ * D_];
__device__ __half g_wlog[(size_t)D_ * V_];

__device__ __forceinline__ uint32_t packh2(float x, float y) {
    __half2 t = __floats2half2_rn(x, y);
    return *reinterpret_cast<uint32_t*>(&t);
}

// ---------------- PTX helpers ----------------------------------------------
__device__ __forceinline__ uint32_t sptr(const void* p) {
    return (uint32_t)__cvta_generic_to_shared(p);
}
#define LDSM4(R0, R1, R2, R3, ADDR) \
    asm volatile("ldmatrix.sync.aligned.m8n8.x4.shared.b16 {%0,%1,%2,%3}, [%4];" \
                 : "=r"(R0), "=r"(R1), "=r"(R2), "=r"(R3) : "r"(ADDR))
#define LDSM4T(R0, R1, R2, R3, ADDR) \
    asm volatile("ldmatrix.sync.aligned.m8n8.x4.trans.shared.b16 {%0,%1,%2,%3}, [%4];" \
                 : "=r"(R0), "=r"(R1), "=r"(R2), "=r"(R3) : "r"(ADDR))
#define MMA16816(Cv, Ar, Bb0, Bb1) \
    asm volatile("mma.sync.aligned.m16n8k16.row.col.f32.f16.f16.f32 " \
                 "{%0,%1,%2,%3},{%4,%5,%6,%7},{%8,%9},{%0,%1,%2,%3};" \
                 : "+f"(Cv[0]), "+f"(Cv[1]), "+f"(Cv[2]), "+f"(Cv[3]) \
                 : "r"(Ar[0]), "r"(Ar[1]), "r"(Ar[2]), "r"(Ar[3]), \
                   "r"(Bb0), "r"(Bb1))
#define EX2X2(D, S) \
    asm volatile("ex2.approx.f16x2 %0, %1;" : "=r"(D) : "r"(S))
#define CP16(DST, SRC) \
    asm volatile("cp.async.cg.shared.global [%0], [%1], 16;" :: "r"(DST), "l"(SRC))
#define CPCOMMIT() asm volatile("cp.async.commit_group;")
#define CPWAIT1()  asm volatile("cp.async.wait_group 1;")
#define CPWAIT2()  asm volatile("cp.async.wait_group 2;")
#define CPWAITALL() asm volatile("cp.async.wait_all;")

#define HALF2_ONES 0x3C003C00u

// ---------------- weight convert: fp32 -> fp16 (same [K][N] layout) -------
__global__ void cvt_kernel(const float* __restrict__ in,
                           __half* __restrict__ hi, int n) {
    int i = (blockIdx.x * 256 + threadIdx.x) * 4;
    if (i >= n) return;
    float4 v = *(const float4*)(in + i);
    *(uint32_t*)(hi + i)     = packh2(v.x, v.y);
    *(uint32_t*)(hi + i + 2) = packh2(v.z, v.w);
}

// ---------------- embedding + positional encoding (+ fp16 out) ------------
__global__ void embed_kernel(const int* __restrict__ tokens,
                             const float* __restrict__ emb,
                             float* __restrict__ x,
                             __half* __restrict__ xh) {
    int row = blockIdx.x;
    int s   = row & (S_ - 1);
    int tok = tokens[row];
    const float* erow = emb + (size_t)tok * D_;
    size_t base = (size_t)row * D_;
    const float kfac = -0.00899447301950812f;   // -ln(10000)/1024
    #pragma unroll
    for (int j = 0; j < 4; ++j) {
        int c = threadIdx.x + j * 256;
        float freq = expf(kfac * (float)(c & ~1));
        float arg  = (float)s * freq;
        float pe   = (c & 1) ? cosf(arg) : sinf(arg);
        float v = erow[c] + pe;
        x[base + c] = v;
        xh[base + c] = __float2half_rn(v);
    }
}

// ===================== fp16 tensor-core GEMM (single-term) =================
// C = Ah[MxK] @ Bh[KxN] + bias, fp32 accum.
// 512 threads = 16 warps (4m x 4n), warp tile 32x64, block tile 128x256x64.
// 4-stage cp.async pipeline, one __syncthreads per k-chunk.
#define AST2 72
#define BST2 264
#define A_EL (128 * AST2)                 // 9216
#define B_EL2 (64 * BST2)                 // 16896
#define STG_E (A_EL + B_EL2)              // 26112 elems
#define GEMM_SMEM (4 * STG_E * 2)         // 208896 bytes

#define ISSUE_STAGE(SIDX, K0) do {                                           \
    __half* _b = sm + (SIDX) * STG_E;                                        \
    _Pragma("unroll")                                                        \
    for (int _i = 0; _i < 2; ++_i) {                                         \
        int _id = tid + _i * 512;                                            \
        int _r = _id >> 3, _c = (_id & 7) << 3;                              \
        CP16(sptr(_b + _r * AST2 + _c), gA + (size_t)_r * K + (K0) + _c);    \
    }                                                                        \
    _Pragma("unroll")                                                        \
    for (int _i = 0; _i < 4; ++_i) {                                         \
        int _id = tid + _i * 512;                                            \
        int _r = _id >> 5, _c = (_id & 31) << 3;                             \
        CP16(sptr(_b + A_EL + _r * BST2 + _c),                               \
             gB + (size_t)((K0) + _r) * N + _c);                             \
    }                                                                        \
} while (0)

// mode 0: fp32 C.
// mode 1: relu + fp16 out.
// mode 2: qkv -> fp16 out, Q columns (col < 1024) pre-scaled by SCALE_LOG2.
__global__ void __launch_bounds__(512, 1)
mma_gemm(const __half* __restrict__ Ah,
         const __half* __restrict__ Bh,
         const float* __restrict__ bias,
         float* __restrict__ C,
         __half* __restrict__ Ch,
         int N, int K, int mode) {
    extern __shared__ __half sm[];

    const int tid = threadIdx.x;
    const int wid = tid >> 5, lane = tid & 31;
    const int wm = (wid >> 2) << 5;     // 0..96
    const int wn = (wid & 3) << 6;      // 0..192
    const int bx = blockIdx.x, by = blockIdx.y;

    const __half* gA = Ah + (size_t)(by * 128) * K;
    const __half* gB = Bh + bx * 256;

    float acc[2][8][4];
    #pragma unroll
    for (int i = 0; i < 2; ++i)
        #pragma unroll
        for (int j = 0; j < 8; ++j)
            #pragma unroll
            for (int t = 0; t < 4; ++t) acc[i][j][t] = 0.f;

    ISSUE_STAGE(0, 0);   CPCOMMIT();
    ISSUE_STAGE(1, 64);  CPCOMMIT();
    ISSUE_STAGE(2, 128); CPCOMMIT();

    const int ntile = K >> 6;
    for (int it = 0; it < ntile; ++it) {
        CPWAIT2();
        __syncthreads();

        int nk = (it + 3) << 6;
        if (nk < K) {
            ISSUE_STAGE((it + 3) & 3, nk);
        }
        CPCOMMIT();

        const __half* ah = sm + (it & 3) * STG_E;
        const __half* bsh = ah + A_EL;

        #pragma unroll
        for (int kc = 0; kc < 4; ++kc) {
            uint32_t a_f[2][4];
            int af = lane & 15;
            int ac = kc * 16 + ((lane >> 4) << 3);
            #pragma unroll
            for (int mt = 0; mt < 2; ++mt) {
                uint32_t ad = sptr(ah + (wm + mt * 16 + af) * AST2 + ac);
                LDSM4(a_f[mt][0], a_f[mt][1], a_f[mt][2], a_f[mt][3], ad);
            }
            int bkr = kc * 16 + (lane & 15);
            #pragma unroll
            for (int p = 0; p < 4; ++p) {
                int bnc = wn + p * 16 + ((lane >> 4) << 3);
                uint32_t b0, b1, b2, b3;
                uint32_t bd = sptr(bsh + bkr * BST2 + bnc);
                LDSM4T(b0, b1, b2, b3, bd);
                MMA16816(acc[0][2*p],   a_f[0], b0, b1);
                MMA16816(acc[0][2*p+1], a_f[0], b2, b3);
                MMA16816(acc[1][2*p],   a_f[1], b0, b1);
                MMA16816(acc[1][2*p+1], a_f[1], b2, b3);
            }
        }
        // no trailing sync: stage (it&3) is rewritten only in iteration it+1,
        // after that iteration's top-of-loop __syncthreads.
    }

    #pragma unroll
    for (int mt = 0; mt < 2; ++mt) {
        int row = by * 128 + wm + mt * 16 + (lane >> 2);
        #pragma unroll
        for (int nt = 0; nt < 8; ++nt) {
            int col = bx * 256 + wn + nt * 8 + ((lane & 3) << 1);
            float2 bv = *(const float2*)(bias + col);
            float v0 = acc[mt][nt][0] + bv.x;
            float v1 = acc[mt][nt][1] + bv.y;
            float v2 = acc[mt][nt][2] + bv.x;
            float v3 = acc[mt][nt][3] + bv.y;
            if (mode == 0) {
                float2 o0 = {v0, v1}, o1 = {v2, v3};
                *(float2*)(C + (size_t)row * N + col)       = o0;
                *(float2*)(C + (size_t)(row + 8) * N + col) = o1;
            } else {
                if (mode == 1) {
                    v0 = fmaxf(v0, 0.f); v1 = fmaxf(v1, 0.f);
                    v2 = fmaxf(v2, 0.f); v3 = fmaxf(v3, 0.f);
                } else if (col < 1024) {   // mode 2: pre-scale Q plane
                    v0 *= SCALE_LOG2; v1 *= SCALE_LOG2;
                    v2 *= SCALE_LOG2; v3 *= SCALE_LOG2;
                }
                *(uint32_t*)(Ch + (size_t)row * N + col)       = packh2(v0, v1);
                *(uint32_t*)(Ch + (size_t)(row + 8) * N + col) = packh2(v2, v3);
            }
        }
    }
}

// ===================== tensor-core causal flash attention ==================
// 128 threads (4 warps), 64 queries of one (b,h), 64-key tiles, double-buffered.
// Q pre-scaled by 0.125*log2(e): scores arrive in log2 domain.
// P via ex2.approx.f16x2; denominator via ones-MMA (exact fp32).
#define APAD 72
#define AQBUF 4608                    // 64*72
#define AKV0 AQBUF                    // after Q
#define AKVSTRIDE (2 * AQBUF)         // kh, vh per stage
#define ATT_SMEM ((AQBUF + 2 * AKVSTRIDE) * 2)   // 46080 bytes

__global__ void __launch_bounds__(128, 3)
attn_mma(const __half* __restrict__ qh,
         __half* __restrict__ oh) {
    extern __shared__ __half sm[];
    const int tid = threadIdx.x;
    const int wid = tid >> 5, lane = tid & 31;
    const int qb = gridDim.x - 1 - blockIdx.x;
    const int bh = blockIdx.y;
    const int h = bh & (H_ - 1), b = bh >> 4;
    const int wq0 = wid << 4;

    const size_t seqbase = (size_t)(b * S_) * 3072 + h * 64;

    // Q tile
    {
        #pragma unroll
        for (int i = 0; i < 4; ++i) {
            int id = tid + i * 128;
            int row = id >> 3, col = (id & 7) << 3;
            size_t src = seqbase + (size_t)(qb * 64 + row) * 3072 + col;
            CP16(sptr(sm + row * APAD + col), qh + src);
        }
        CPCOMMIT();
    }
    #define ISSUE_KV(STG, KT0) do {                                         \
        __half* _kb = sm + AKV0 + (STG) * AKVSTRIDE;                        \
        _Pragma("unroll")                                                   \
        for (int i = 0; i < 4; ++i) {                                       \
            int id = tid + i * 128;                                         \
            int row = id >> 3, col = (id & 7) << 3;                         \
            size_t src = seqbase + (size_t)((KT0) * 64 + row) * 3072 + col; \
            uint32_t dst = sptr(_kb + row * APAD + col);                    \
            CP16(dst,              qh + src + 1024);                        \
            CP16(dst + AQBUF * 2,  qh + src + 2048);                        \
        }                                                                   \
        CPCOMMIT();                                                         \
    } while (0)

    ISSUE_KV(0, 0);
    ISSUE_KV(1, (qb >= 1 ? 1 : 0));

    CPWAIT2();
    __syncthreads();
    uint32_t qf[4][4];
    {
        int af = lane & 15;
        #pragma unroll
        for (int kc = 0; kc < 4; ++kc) {
            int ac = kc * 16 + ((lane >> 4) << 3);
            uint32_t ad = sptr(sm + (wq0 + af) * APAD + ac);
            LDSM4(qf[kc][0], qf[kc][1], qf[kc][2], qf[kc][3], ad);
        }
    }

    float Od[8][4];
    #pragma unroll
    for (int i = 0; i < 8; ++i)
        #pragma unroll
        for (int j = 0; j < 4; ++j) Od[i][j] = 0.f;
    float dacc[4] = {0.f, 0.f, 0.f, 0.f};       // denominator accumulator (MMA)
    float m_a = -1e30f, m_b = -1e30f;

    int buf = 0;
    const int ntk = qb + 1;
    for (int kt = 0; kt < ntk; ++kt) {
        CPWAIT1();
        __syncthreads();

        const __half* kh = sm + AKV0 + buf * AKVSTRIDE;
        const __half* vh = kh + AQBUF;

        float sreg[8][4];
        #pragma unroll
        for (int i = 0; i < 8; ++i)
            #pragma unroll
            for (int j = 0; j < 4; ++j) sreg[i][j] = 0.f;

        #pragma unroll
        for (int kc = 0; kc < 4; ++kc) {
            int krow = ((lane >> 4) << 3) + (lane & 7);
            int kcol = kc * 16 + (((lane >> 3) & 1) << 3);
            #pragma unroll
            for (int ng = 0; ng < 4; ++ng) {
                uint32_t bh0, bh1, bh2, bh3;
                uint32_t ad = sptr(kh + (ng * 16 + krow) * APAD + kcol);
                LDSM4(bh0, bh1, bh2, bh3, ad);
                MMA16816(sreg[2*ng],   qf[kc], bh0, bh1);
                MMA16816(sreg[2*ng+1], qf[kc], bh2, bh3);
            }
        }

        // causal mask only in the final tile (scores already log2-scaled)
        if (kt == qb) {
            int ra = wq0 + (lane >> 2);
            int cb = (lane & 3) << 1;
            #pragma unroll
            for (int nt = 0; nt < 8; ++nt) {
                #pragma unroll
                for (int j = 0; j < 4; ++j) {
                    int col = nt * 8 + cb + (j & 1);
                    int row = ra + ((j >> 1) << 3);
                    if (col > row) sreg[nt][j] = -1e30f;
                }
            }
        }
        // row max (log2 domain)
        float mxa = -1e30f, mxb = -1e30f;
        #pragma unroll
        for (int nt = 0; nt < 8; ++nt) {
            mxa = fmaxf(mxa, fmaxf(sreg[nt][0], sreg[nt][1]));
            mxb = fmaxf(mxb, fmaxf(sreg[nt][2], sreg[nt][3]));
        }
        mxa = fmaxf(mxa, __shfl_xor_sync(0xffffffffu, mxa, 1));
        mxa = fmaxf(mxa, __shfl_xor_sync(0xffffffffu, mxa, 2));
        mxb = fmaxf(mxb, __shfl_xor_sync(0xffffffffu, mxb, 1));
        mxb = fmaxf(mxb, __shfl_xor_sync(0xffffffffu, mxb, 2));
        float mna = fmaxf(m_a, mxa), mnb = fmaxf(m_b, mxb);
        float ca = exp2f(m_a - mna), cbr = exp2f(m_b - mnb);
        m_a = mna; m_b = mnb;
        #pragma unroll
        for (int nt = 0; nt < 8; ++nt) {
            Od[nt][0] *= ca;  Od[nt][1] *= ca;
            Od[nt][2] *= cbr; Od[nt][3] *= cbr;
        }
        dacc[0] *= ca;  dacc[1] *= ca;
        dacc[2] *= cbr; dacc[3] *= cbr;

        // P = 2^(s - m) as fp16 pairs; denominator via ones-MMA; O += P @ Vh
        #pragma unroll
        for (int kc2 = 0; kc2 < 4; ++kc2) {
            uint32_t ph[4];
            uint32_t t0 = packh2(sreg[2*kc2][0]   - mna, sreg[2*kc2][1]   - mna);
            uint32_t t1 = packh2(sreg[2*kc2][2]   - mnb, sreg[2*kc2][3]   - mnb);
            uint32_t t2 = packh2(sreg[2*kc2+1][0] - mna, sreg[2*kc2+1][1] - mna);
            uint32_t t3 = packh2(sreg[2*kc2+1][2] - mnb, sreg[2*kc2+1][3] - mnb);
            EX2X2(ph[0], t0);
            EX2X2(ph[1], t1);
            EX2X2(ph[2], t2);
            EX2X2(ph[3], t3);
            MMA16816(dacc, ph, HALF2_ONES, HALF2_ONES);
            int vr = kc2 * 16 + (lane & 15);
            #pragma unroll
            for (int ng = 0; ng < 4; ++ng) {
                int vc = ng * 16 + ((lane >> 4) << 3);
                uint32_t v0, v1, v2, v3;
                uint32_t ad = sptr(vh + vr * APAD + vc);
                LDSM4T(v0, v1, v2, v3, ad);
                MMA16816(Od[2*ng],   ph, v0, v1);
                MMA16816(Od[2*ng+1], ph, v2, v3);
            }
        }
        __syncthreads();
        if (kt + 2 <= qb) ISSUE_KV(buf, kt + 2);
        CPCOMMIT();
        buf ^= 1;
    }

    CPWAITALL();

    // all n-columns of the ones-MMA result are identical -> dacc[0]/dacc[2]
    // hold the row sums for rows ra and ra+8 in every thread of the quad.
    float inva = 1.f / dacc[0], invb = 1.f / dacc[2];
    int gq_a = qb * 64 + wq0 + (lane >> 2);
    size_t oa = (size_t)(b * S_ + gq_a) * D_ + h * 64 + ((lane & 3) << 1);
    size_t ob = oa + (size_t)8 * D_;
    #pragma unroll
    for (int nt = 0; nt < 8; ++nt) {
        *(uint32_t*)(oh + oa + nt * 8) = packh2(Od[nt][0] * inva, Od[nt][1] * inva);
        *(uint32_t*)(oh + ob + nt * 8) = packh2(Od[nt][2] * invb, Od[nt][3] * invb);
    }
}

// ---------------- fused residual add + LayerNorm (single-pass reduce) -----
__global__ void add_ln_kernel(float* __restrict__ x,
                              const float* __restrict__ r,
                              const float* __restrict__ g,
                              const float* __restrict__ bb,
                              __half* __restrict__ xh) {
    int row = blockIdx.x;
    int tid = threadIdx.x;
    size_t base = (size_t)row * D_;
    float v[4];
    float s = 0.f, sq = 0.f;
    #pragma unroll
    for (int j = 0; j < 4; ++j) {
        int c = tid + j * 256;
        v[j] = x[base + c] + r[base + c];
        s += v[j];
        sq = fmaf(v[j], v[j], sq);
    }
    __shared__ float sh_s[8], sh_q[8];
    #pragma unroll
    for (int off = 16; off > 0; off >>= 1) {
        s  += __shfl_xor_sync(0xffffffffu, s, off);
        sq += __shfl_xor_sync(0xffffffffu, sq, off);
    }
    if ((tid & 31) == 0) { sh_s[tid >> 5] = s; sh_q[tid >> 5] = sq; }
    __syncthreads();
    if (tid < 32) {
        float t  = (tid < 8) ? sh_s[tid] : 0.f;
        float tq = (tid < 8) ? sh_q[tid] : 0.f;
        #pragma unroll
        for (int off = 4; off > 0; off >>= 1) {
            t  += __shfl_xor_sync(0xffffffffu, t, off);
            tq += __shfl_xor_sync(0xffffffffu, tq, off);
        }
        if (tid == 0) { sh_s[0] = t; sh_q[0] = tq; }
    }
    __syncthreads();
    float mu  = sh_s[0] * (1.f / 1024.f);
    float var = sh_q[0] * (1.f / 1024.f) - mu * mu;
    float rstd = rsqrtf(var + 1e-5f);
    #pragma unroll
    for (int j = 0; j < 4; ++j) {
        int c = tid + j * 256;
        float y = (v[j] - mu) * rstd * g[c] + bb[c];
        x[base + c] = y;
        xh[base + c] = __float2half_rn(y);
    }
}

// ---------------------------------------------------------------------------
extern "C" void kernel_launch(void* const* d_in, const int* in_sizes, int n_in,
                              void* d_out, int out_size) {
    const int*   tokens = (const int*)  d_in[0];
    const float* emb    = (const float*)d_in[1];
    const float* qkv_w  = (const float*)d_in[2];
    const float* qkv_b  = (const float*)d_in[3];
    const float* out_w  = (const float*)d_in[4];
    const float* out_b  = (const float*)d_in[5];
    const float* fc1_w  = (const float*)d_in[6];
    const float* fc1_b  = (const float*)d_in[7];
    const float* fc2_w  = (const float*)d_in[8];
    const float* fc2_b  = (const float*)d_in[9];
    const float* ln1_g  = (const float*)d_in[10];
    const float* ln1_b  = (const float*)d_in[11];
    const float* ln2_g  = (const float*)d_in[12];
    const float* ln2_b  = (const float*)d_in[13];
    const float* w_out  = (const float*)d_in[14];
    const float* b_out  = (const float*)d_in[15];
    float* out = (float*)d_out;

    float *x, *tmp, *o;
    __half *xh, *oh, *hh, *wqkv, *wout, *wfc1, *wfc2, *wlog;
    cudaGetSymbolAddress((void**)&x,    g_x);
    cudaGetSymbolAddress((void**)&tmp,  g_tmp);
    cudaGetSymbolAddress((void**)&o,    g_o);
    cudaGetSymbolAddress((void**)&xh,   g_xh);
    cudaGetSymbolAddress((void**)&oh,   g_oh);
    cudaGetSymbolAddress((void**)&hh,   g_hh);
    cudaGetSymbolAddress((void**)&wqkv, g_wqkv);
    cudaGetSymbolAddress((void**)&wout, g_wout);
    cudaGetSymbolAddress((void**)&wfc1, g_wfc1);
    cudaGetSymbolAddress((void**)&wfc2, g_wfc2);
    cudaGetSymbolAddress((void**)&wlog, g_wlog);

    cudaFuncSetAttribute(mma_gemm, cudaFuncAttributeMaxDynamicSharedMemorySize,
                         GEMM_SMEM);
    cudaFuncSetAttribute(attn_mma, cudaFuncAttributeMaxDynamicSharedMemorySize,
                         ATT_SMEM);

    // ---- preconvert all weights (once per replay, fully parallel)
    {
        int n;
        n = L_ * D_ * 3 * D_;  cvt_kernel<<<n / 1024, 256>>>(qkv_w, wqkv, n);
        n = L_ * D_ * D_;      cvt_kernel<<<n / 1024, 256>>>(out_w, wout, n);
        n = L_ * D_ * FF_;     cvt_kernel<<<n / 1024, 256>>>(fc1_w, wfc1, n);
        n = L_ * FF_ * D_;     cvt_kernel<<<n / 1024, 256>>>(fc2_w, wfc2, n);
        n = D_ * V_;           cvt_kernel<<<n / 1024, 256>>>(w_out, wlog, n);
    }

    embed_kernel<<<TOK_, 256>>>(tokens, emb, x, xh);

    for (int l = 0; l < L_; ++l) {
        // qkv = x @ qkv_w + b -> fp16 (mode 2, Q pre-scaled) into hh
        mma_gemm<<<dim3(3072 / 256, TOK_ / 128), 512, GEMM_SMEM>>>(
            xh, wqkv + (size_t)l * D_ * 3 * D_, qkv_b + (size_t)l * 3 * D_,
            nullptr, hh, 3 * D_, D_, 2);
        // attention -> oh
        attn_mma<<<dim3(S_ / 64, B_ * H_), 128, ATT_SMEM>>>(hh, oh);
        // out proj -> tmp fp32
        mma_gemm<<<dim3(D_ / 256, TOK_ / 128), 512, GEMM_SMEM>>>(
            oh, wout + (size_t)l * D_ * D_, out_b + (size_t)l * D_,
            tmp, nullptr, D_, D_, 0);
        add_ln_kernel<<<TOK_, 256>>>(x, tmp, ln1_g + l * D_, ln1_b + l * D_, xh);
        // fc1 (relu, fp16)
        mma_gemm<<<dim3(FF_ / 256, TOK_ / 128), 512, GEMM_SMEM>>>(
            xh, wfc1 + (size_t)l * D_ * FF_, fc1_b + (size_t)l * FF_,
            nullptr, hh, FF_, D_, 1);
        // fc2
        mma_gemm<<<dim3(D_ / 256, TOK_ / 128), 512, GEMM_SMEM>>>(
            hh, wfc2 + (size_t)l * FF_ * D_, fc2_b + (size_t)l * D_,
            o, nullptr, D_, FF_, 0);
        add_ln_kernel<<<TOK_, 256>>>(x, o, ln2_g + l * D_, ln2_b + l * D_, xh);
    }

    // logits
    mma_gemm<<<dim3(V_ / 256, TOK_ / 128), 512, GEMM_SMEM>>>(
        xh, wlog, b_out, out, nullptr, V_, D_, 0);
}

// round 15
// speedup vs baseline: 1.0365x; 1.0365x over previous
#include <cuda_runtime.h>
#include <cuda_fp16.h>
#include <math.h>
#include <stdint.h>

#define B_ 2
#define S_ 2048
#define D_ 1024
#define L_ 6
#define H_ 16
#define HD_ 64
#define FF_ 4096
#define V_ 32000
#define TOK_ (B_ * S_)          // 4096 token rows

#define SCALE_LOG2 0.1803368801111f   // 0.125 * log2(e)

// ---------------- scratch (static device globals; no allocation) ----------
__device__ float g_x[TOK_ * D_];                 // fp32 residual stream
__device__ float g_tmp[TOK_ * FF_];              // out-proj / fc2 fp32 out
__device__ float g_o[TOK_ * D_];                 // fc2 out (pre-LN2)
__device__ __half g_xh[TOK_ * D_];               // x (fp16 plane)
__device__ __half g_oh[TOK_ * D_];               // attention out
__device__ __half g_hh[TOK_ * FF_];              // qkv / ffn hidden (fp16)
// preconverted fp16 weights, layout [K][N] per layer
__device__ __half g_wqkv[(size_t)L_ * D_ * 3 * D_];
__device__ __half g_wout[(size_t)L_ * D_ * D_];
__device__ __half g_wfc1[(size_t)L_ * D_ * FF_];
__device__ __half g_wfc2[(size_t)L_ * FF_ * D_];
__device__ __half g_wlog[(size_t)D_ * V_];

__device__ __forceinline__ uint32_t packh2(float x, float y) {
    __half2 t = __floats2half2_rn(x, y);
    return *reinterpret_cast<uint32_t*>(&t);
}

// ---------------- PTX helpers ----------------------------------------------
__device__ __forceinline__ uint32_t sptr(const void* p) {
    return (uint32_t)__cvta_generic_to_shared(p);
}
#define LDSM4(R0, R1, R2, R3, ADDR) \
    asm volatile("ldmatrix.sync.aligned.m8n8.x4.shared.b16 {%0,%1,%2,%3}, [%4];" \
                 : "=r"(R0), "=r"(R1), "=r"(R2), "=r"(R3) : "r"(ADDR))
#define LDSM4T(R0, R1, R2, R3, ADDR) \
    asm volatile("ldmatrix.sync.aligned.m8n8.x4.trans.shared.b16 {%0,%1,%2,%3}, [%4];" \
                 : "=r"(R0), "=r"(R1), "=r"(R2), "=r"(R3) : "r"(ADDR))
#define MMA16816(Cv, Ar, Bb0, Bb1) \
    asm volatile("mma.sync.aligned.m16n8k16.row.col.f32.f16.f16.f32 " \
                 "{%0,%1,%2,%3},{%4,%5,%6,%7},{%8,%9},{%0,%1,%2,%3};" \
                 : "+f"(Cv[0]), "+f"(Cv[1]), "+f"(Cv[2]), "+f"(Cv[3]) \
                 : "r"(Ar[0]), "r"(Ar[1]), "r"(Ar[2]), "r"(Ar[3]), \
                   "r"(Bb0), "r"(Bb1))
#define EX2X2(D, S) \
    asm volatile("ex2.approx.f16x2 %0, %1;" : "=r"(D) : "r"(S))
#define CP16(DST, SRC) \
    asm volatile("cp.async.cg.shared.global [%0], [%1], 16;" :: "r"(DST), "l"(SRC))
#define CPCOMMIT() asm volatile("cp.async.commit_group;")
#define CPWAIT1()  asm volatile("cp.async.wait_group 1;")
#define CPWAIT2()  asm volatile("cp.async.wait_group 2;")
#define CPWAITALL() asm volatile("cp.async.wait_all;")

#define HALF2_ONES 0x3C003C00u

// ---------------- weight convert: fp32 -> fp16 (same [K][N] layout) -------
__global__ void cvt_kernel(const float* __restrict__ in,
                           __half* __restrict__ hi, int n) {
    int i = (blockIdx.x * 256 + threadIdx.x) * 4;
    if (i >= n) return;
    float4 v = *(const float4*)(in + i);
    *(uint32_t*)(hi + i)     = packh2(v.x, v.y);
    *(uint32_t*)(hi + i + 2) = packh2(v.z, v.w);
}

// ---------------- embedding + positional encoding (+ fp16 out) ------------
__global__ void embed_kernel(const int* __restrict__ tokens,
                             const float* __restrict__ emb,
                             float* __restrict__ x,
                             __half* __restrict__ xh) {
    int row = blockIdx.x;
    int s   = row & (S_ - 1);
    int tok = tokens[row];
    const float* erow = emb + (size_t)tok * D_;
    size_t base = (size_t)row * D_;
    const float kfac = -0.00899447301950812f;   // -ln(10000)/1024
    #pragma unroll
    for (int j = 0; j < 4; ++j) {
        int c = threadIdx.x + j * 256;
        float freq = expf(kfac * (float)(c & ~1));
        float arg  = (float)s * freq;
        float pe   = (c & 1) ? cosf(arg) : sinf(arg);
        float v = erow[c] + pe;
        x[base + c] = v;
        xh[base + c] = __float2half_rn(v);
    }
}

// ===================== fp16 tensor-core GEMM (single-term) =================
// C = Ah[MxK] @ Bh[KxN] + bias, fp32 accum.
// 512 threads = 16 warps (4m x 4n), warp tile 32x64, block tile 128x256x64.
// 4-stage cp.async pipeline, one __syncthreads per k-chunk.
#define AST2 72
#define BST2 264
#define A_EL (128 * AST2)                 // 9216
#define B_EL2 (64 * BST2)                 // 16896
#define STG_E (A_EL + B_EL2)              // 26112 elems
#define GEMM_SMEM (4 * STG_E * 2)         // 208896 bytes

#define ISSUE_STAGE(SIDX, K0) do {                                           \
    __half* _b = sm + (SIDX) * STG_E;                                        \
    _Pragma("unroll")                                                        \
    for (int _i = 0; _i < 2; ++_i) {                                         \
        int _id = tid + _i * 512;                                            \
        int _r = _id >> 3, _c = (_id & 7) << 3;                              \
        CP16(sptr(_b + _r * AST2 + _c), gA + (size_t)_r * K + (K0) + _c);    \
    }                                                                        \
    _Pragma("unroll")                                                        \
    for (int _i = 0; _i < 4; ++_i) {                                         \
        int _id = tid + _i * 512;                                            \
        int _r = _id >> 5, _c = (_id & 31) << 3;                             \
        CP16(sptr(_b + A_EL + _r * BST2 + _c),                               \
             gB + (size_t)((K0) + _r) * N + _c);                             \
    }                                                                        \
} while (0)

// mode 0: fp32 C. mode 1: relu + fp16. mode 2: fp16 (no relu).
__global__ void __launch_bounds__(512, 1)
mma_gemm(const __half* __restrict__ Ah,
         const __half* __restrict__ Bh,
         const float* __restrict__ bias,
         float* __restrict__ C,
         __half* __restrict__ Ch,
         int N, int K, int mode) {
    extern __shared__ __half sm[];

    const int tid = threadIdx.x;
    const int wid = tid >> 5, lane = tid & 31;
    const int wm = (wid >> 2) << 5;     // 0..96
    const int wn = (wid & 3) << 6;      // 0..192
    const int bx = blockIdx.x, by = blockIdx.y;

    const __half* gA = Ah + (size_t)(by * 128) * K;
    const __half* gB = Bh + bx * 256;

    float acc[2][8][4];
    #pragma unroll
    for (int i = 0; i < 2; ++i)
        #pragma unroll
        for (int j = 0; j < 8; ++j)
            #pragma unroll
            for (int t = 0; t < 4; ++t) acc[i][j][t] = 0.f;

    ISSUE_STAGE(0, 0);   CPCOMMIT();
    ISSUE_STAGE(1, 64);  CPCOMMIT();
    ISSUE_STAGE(2, 128); CPCOMMIT();

    const int ntile = K >> 6;
    for (int it = 0; it < ntile; ++it) {
        CPWAIT2();
        __syncthreads();

        int nk = (it + 3) << 6;
        if (nk < K) {
            ISSUE_STAGE((it + 3) & 3, nk);
        }
        CPCOMMIT();

        const __half* ah = sm + (it & 3) * STG_E;
        const __half* bsh = ah + A_EL;

        #pragma unroll
        for (int kc = 0; kc < 4; ++kc) {
            uint32_t a_f[2][4];
            int af = lane & 15;
            int ac = kc * 16 + ((lane >> 4) << 3);
            #pragma unroll
            for (int mt = 0; mt < 2; ++mt) {
                uint32_t ad = sptr(ah + (wm + mt * 16 + af) * AST2 + ac);
                LDSM4(a_f[mt][0], a_f[mt][1], a_f[mt][2], a_f[mt][3], ad);
            }
            int bkr = kc * 16 + (lane & 15);
            #pragma unroll
            for (int p = 0; p < 4; ++p) {
                int bnc = wn + p * 16 + ((lane >> 4) << 3);
                uint32_t b0, b1, b2, b3;
                uint32_t bd = sptr(bsh + bkr * BST2 + bnc);
                LDSM4T(b0, b1, b2, b3, bd);
                MMA16816(acc[0][2*p],   a_f[0], b0, b1);
                MMA16816(acc[0][2*p+1], a_f[0], b2, b3);
                MMA16816(acc[1][2*p],   a_f[1], b0, b1);
                MMA16816(acc[1][2*p+1], a_f[1], b2, b3);
            }
        }
        // no trailing sync: stage (it&3) is rewritten only in iteration it+1,
        // after that iteration's top-of-loop __syncthreads.
    }

    #pragma unroll
    for (int mt = 0; mt < 2; ++mt) {
        int row = by * 128 + wm + mt * 16 + (lane >> 2);
        #pragma unroll
        for (int nt = 0; nt < 8; ++nt) {
            int col = bx * 256 + wn + nt * 8 + ((lane & 3) << 1);
            float2 bv = *(const float2*)(bias + col);
            float v0 = acc[mt][nt][0] + bv.x;
            float v1 = acc[mt][nt][1] + bv.y;
            float v2 = acc[mt][nt][2] + bv.x;
            float v3 = acc[mt][nt][3] + bv.y;
            if (mode == 0) {
                float2 o0 = {v0, v1}, o1 = {v2, v3};
                *(float2*)(C + (size_t)row * N + col)       = o0;
                *(float2*)(C + (size_t)(row + 8) * N + col) = o1;
            } else {
                if (mode == 1) {
                    v0 = fmaxf(v0, 0.f); v1 = fmaxf(v1, 0.f);
                    v2 = fmaxf(v2, 0.f); v3 = fmaxf(v3, 0.f);
                }
                *(uint32_t*)(Ch + (size_t)row * N + col)       = packh2(v0, v1);
                *(uint32_t*)(Ch + (size_t)(row + 8) * N + col) = packh2(v2, v3);
            }
        }
    }
}

// ===================== tensor-core causal flash attention ==================
// 128 threads (4 warps), 64 queries of one (b,h), 64-key tiles, double-buffered.
// log2-domain softmax: scale = 0.125*log2(e); P via ex2.approx.f16x2;
// denominator via extra MMA against all-ones B fragment (exact fp32).
#define APAD 72
#define AQBUF 4608                    // 64*72
#define AKV0 AQBUF                    // after Q
#define AKVSTRIDE (2 * AQBUF)         // kh, vh per stage
#define ATT_SMEM ((AQBUF + 2 * AKVSTRIDE) * 2)   // 46080 bytes

__global__ void __launch_bounds__(128, 3)
attn_mma(const __half* __restrict__ qh,
         __half* __restrict__ oh) {
    extern __shared__ __half sm[];
    const int tid = threadIdx.x;
    const int wid = tid >> 5, lane = tid & 31;
    const int qb = gridDim.x - 1 - blockIdx.x;
    const int bh = blockIdx.y;
    const int h = bh & (H_ - 1), b = bh >> 4;
    const int wq0 = wid << 4;

    const size_t seqbase = (size_t)(b * S_) * 3072 + h * 64;

    // Q tile
    {
        #pragma unroll
        for (int i = 0; i < 4; ++i) {
            int id = tid + i * 128;
            int row = id >> 3, col = (id & 7) << 3;
            size_t src = seqbase + (size_t)(qb * 64 + row) * 3072 + col;
            CP16(sptr(sm + row * APAD + col), qh + src);
        }
        CPCOMMIT();
    }
    #define ISSUE_KV(STG, KT0) do {                                         \
        __half* _kb = sm + AKV0 + (STG) * AKVSTRIDE;                        \
        _Pragma("unroll")                                                   \
        for (int i = 0; i < 4; ++i) {                                       \
            int id = tid + i * 128;                                         \
            int row = id >> 3, col = (id & 7) << 3;                         \
            size_t src = seqbase + (size_t)((KT0) * 64 + row) * 3072 + col; \
            uint32_t dst = sptr(_kb + row * APAD + col);                    \
            CP16(dst,              qh + src + 1024);                        \
            CP16(dst + AQBUF * 2,  qh + src + 2048);                        \
        }                                                                   \
        CPCOMMIT();                                                         \
    } while (0)

    ISSUE_KV(0, 0);
    ISSUE_KV(1, (qb >= 1 ? 1 : 0));

    CPWAIT2();
    __syncthreads();
    uint32_t qf[4][4];
    {
        int af = lane & 15;
        #pragma unroll
        for (int kc = 0; kc < 4; ++kc) {
            int ac = kc * 16 + ((lane >> 4) << 3);
            uint32_t ad = sptr(sm + (wq0 + af) * APAD + ac);
            LDSM4(qf[kc][0], qf[kc][1], qf[kc][2], qf[kc][3], ad);
        }
    }

    float Od[8][4];
    #pragma unroll
    for (int i = 0; i < 8; ++i)
        #pragma unroll
        for (int j = 0; j < 4; ++j) Od[i][j] = 0.f;
    float dacc[4] = {0.f, 0.f, 0.f, 0.f};       // denominator accumulator (MMA)
    float m_a = -1e30f, m_b = -1e30f;

    int buf = 0;
    const int ntk = qb + 1;
    for (int kt = 0; kt < ntk; ++kt) {
        CPWAIT1();
        __syncthreads();

        const __half* kh = sm + AKV0 + buf * AKVSTRIDE;
        const __half* vh = kh + AQBUF;

        float sreg[8][4];
        #pragma unroll
        for (int i = 0; i < 8; ++i)
            #pragma unroll
            for (int j = 0; j < 4; ++j) sreg[i][j] = 0.f;

        #pragma unroll
        for (int kc = 0; kc < 4; ++kc) {
            int krow = ((lane >> 4) << 3) + (lane & 7);
            int kcol = kc * 16 + (((lane >> 3) & 1) << 3);
            #pragma unroll
            for (int ng = 0; ng < 4; ++ng) {
                uint32_t bh0, bh1, bh2, bh3;
                uint32_t ad = sptr(kh + (ng * 16 + krow) * APAD + kcol);
                LDSM4(bh0, bh1, bh2, bh3, ad);
                MMA16816(sreg[2*ng],   qf[kc], bh0, bh1);
                MMA16816(sreg[2*ng+1], qf[kc], bh2, bh3);
            }
        }

        // scale to log2 domain + causal mask
        int ra = wq0 + (lane >> 2);
        int cb = (lane & 3) << 1;
        #pragma unroll
        for (int nt = 0; nt < 8; ++nt) {
            #pragma unroll
            for (int j = 0; j < 4; ++j) {
                float s = sreg[nt][j] * SCALE_LOG2;
                if (kt == qb) {
                    int col = nt * 8 + cb + (j & 1);
                    int row = ra + ((j >> 1) << 3);
                    if (col > row) s = -1e30f;
                }
                sreg[nt][j] = s;
            }
        }
        // row max (log2 domain)
        float mxa = -1e30f, mxb = -1e30f;
        #pragma unroll
        for (int nt = 0; nt < 8; ++nt) {
            mxa = fmaxf(mxa, fmaxf(sreg[nt][0], sreg[nt][1]));
            mxb = fmaxf(mxb, fmaxf(sreg[nt][2], sreg[nt][3]));
        }
        mxa = fmaxf(mxa, __shfl_xor_sync(0xffffffffu, mxa, 1));
        mxa = fmaxf(mxa, __shfl_xor_sync(0xffffffffu, mxa, 2));
        mxb = fmaxf(mxb, __shfl_xor_sync(0xffffffffu, mxb, 1));
        mxb = fmaxf(mxb, __shfl_xor_sync(0xffffffffu, mxb, 2));
        float mna = fmaxf(m_a, mxa), mnb = fmaxf(m_b, mxb);
        float ca = exp2f(m_a - mna), cbr = exp2f(m_b - mnb);
        m_a = mna; m_b = mnb;
        #pragma unroll
        for (int nt = 0; nt < 8; ++nt) {
            Od[nt][0] *= ca;  Od[nt][1] *= ca;
            Od[nt][2] *= cbr; Od[nt][3] *= cbr;
        }
        dacc[0] *= ca;  dacc[1] *= ca;
        dacc[2] *= cbr; dacc[3] *= cbr;

        // P = 2^(s - m) directly as fp16 pairs; denominator via ones-MMA;
        // O += P @ Vh
        #pragma unroll
        for (int kc2 = 0; kc2 < 4; ++kc2) {
            uint32_t ph[4];
            uint32_t t0 = packh2(sreg[2*kc2][0]   - mna, sreg[2*kc2][1]   - mna);
            uint32_t t1 = packh2(sreg[2*kc2][2]   - mnb, sreg[2*kc2][3]   - mnb);
            uint32_t t2 = packh2(sreg[2*kc2+1][0] - mna, sreg[2*kc2+1][1] - mna);
            uint32_t t3 = packh2(sreg[2*kc2+1][2] - mnb, sreg[2*kc2+1][3] - mnb);
            EX2X2(ph[0], t0);
            EX2X2(ph[1], t1);
            EX2X2(ph[2], t2);
            EX2X2(ph[3], t3);
            MMA16816(dacc, ph, HALF2_ONES, HALF2_ONES);
            int vr = kc2 * 16 + (lane & 15);
            #pragma unroll
            for (int ng = 0; ng < 4; ++ng) {
                int vc = ng * 16 + ((lane >> 4) << 3);
                uint32_t v0, v1, v2, v3;
                uint32_t ad = sptr(vh + vr * APAD + vc);
                LDSM4T(v0, v1, v2, v3, ad);
                MMA16816(Od[2*ng],   ph, v0, v1);
                MMA16816(Od[2*ng+1], ph, v2, v3);
            }
        }
        __syncthreads();
        if (kt + 2 <= qb) ISSUE_KV(buf, kt + 2);
        CPCOMMIT();
        buf ^= 1;
    }

    CPWAITALL();

    // all n-columns of the ones-MMA result are identical -> dacc[0]/dacc[2]
    // hold the row sums for rows ra and ra+8 in every thread of the quad.
    float inva = 1.f / dacc[0], invb = 1.f / dacc[2];
    int gq_a = qb * 64 + wq0 + (lane >> 2);
    size_t oa = (size_t)(b * S_ + gq_a) * D_ + h * 64 + ((lane & 3) << 1);
    size_t ob = oa + (size_t)8 * D_;
    #pragma unroll
    for (int nt = 0; nt < 8; ++nt) {
        *(uint32_t*)(oh + oa + nt * 8) = packh2(Od[nt][0] * inva, Od[nt][1] * inva);
        *(uint32_t*)(oh + ob + nt * 8) = packh2(Od[nt][2] * invb, Od[nt][3] * invb);
    }
}

// ---------------- fused residual add + LayerNorm (single-pass reduce) -----
__global__ void add_ln_kernel(float* __restrict__ x,
                              const float* __restrict__ r,
                              const float* __restrict__ g,
                              const float* __restrict__ bb,
                              __half* __restrict__ xh) {
    int row = blockIdx.x;
    int tid = threadIdx.x;
    size_t base = (size_t)row * D_;
    float v[4];
    float s = 0.f, sq = 0.f;
    #pragma unroll
    for (int j = 0; j < 4; ++j) {
        int c = tid + j * 256;
        v[j] = x[base + c] + r[base + c];
        s += v[j];
        sq = fmaf(v[j], v[j], sq);
    }
    __shared__ float sh_s[8], sh_q[8];
    #pragma unroll
    for (int off = 16; off > 0; off >>= 1) {
        s  += __shfl_xor_sync(0xffffffffu, s, off);
        sq += __shfl_xor_sync(0xffffffffu, sq, off);
    }
    if ((tid & 31) == 0) { sh_s[tid >> 5] = s; sh_q[tid >> 5] = sq; }
    __syncthreads();
    if (tid < 32) {
        float t  = (tid < 8) ? sh_s[tid] : 0.f;
        float tq = (tid < 8) ? sh_q[tid] : 0.f;
        #pragma unroll
        for (int off = 4; off > 0; off >>= 1) {
            t  += __shfl_xor_sync(0xffffffffu, t, off);
            tq += __shfl_xor_sync(0xffffffffu, tq, off);
        }
        if (tid == 0) { sh_s[0] = t; sh_q[0] = tq; }
    }
    __syncthreads();
    float mu  = sh_s[0] * (1.f / 1024.f);
    float var = sh_q[0] * (1.f / 1024.f) - mu * mu;
    float rstd = rsqrtf(var + 1e-5f);
    #pragma unroll
    for (int j = 0; j < 4; ++j) {
        int c = tid + j * 256;
        float y = (v[j] - mu) * rstd * g[c] + bb[c];
        x[base + c] = y;
        xh[base + c] = __float2half_rn(y);
    }
}

// ---------------------------------------------------------------------------
extern "C" void kernel_launch(void* const* d_in, const int* in_sizes, int n_in,
                              void* d_out, int out_size) {
    const int*   tokens = (const int*)  d_in[0];
    const float* emb    = (const float*)d_in[1];
    const float* qkv_w  = (const float*)d_in[2];
    const float* qkv_b  = (const float*)d_in[3];
    const float* out_w  = (const float*)d_in[4];
    const float* out_b  = (const float*)d_in[5];
    const float* fc1_w  = (const float*)d_in[6];
    const float* fc1_b  = (const float*)d_in[7];
    const float* fc2_w  = (const float*)d_in[8];
    const float* fc2_b  = (const float*)d_in[9];
    const float* ln1_g  = (const float*)d_in[10];
    const float* ln1_b  = (const float*)d_in[11];
    const float* ln2_g  = (const float*)d_in[12];
    const float* ln2_b  = (const float*)d_in[13];
    const float* w_out  = (const float*)d_in[14];
    const float* b_out  = (const float*)d_in[15];
    float* out = (float*)d_out;

    float *x, *tmp, *o;
    __half *xh, *oh, *hh, *wqkv, *wout, *wfc1, *wfc2, *wlog;
    cudaGetSymbolAddress((void**)&x,    g_x);
    cudaGetSymbolAddress((void**)&tmp,  g_tmp);
    cudaGetSymbolAddress((void**)&o,    g_o);
    cudaGetSymbolAddress((void**)&xh,   g_xh);
    cudaGetSymbolAddress((void**)&oh,   g_oh);
    cudaGetSymbolAddress((void**)&hh,   g_hh);
    cudaGetSymbolAddress((void**)&wqkv, g_wqkv);
    cudaGetSymbolAddress((void**)&wout, g_wout);
    cudaGetSymbolAddress((void**)&wfc1, g_wfc1);
    cudaGetSymbolAddress((void**)&wfc2, g_wfc2);
    cudaGetSymbolAddress((void**)&wlog, g_wlog);

    cudaFuncSetAttribute(mma_gemm, cudaFuncAttributeMaxDynamicSharedMemorySize,
                         GEMM_SMEM);
    cudaFuncSetAttribute(attn_mma, cudaFuncAttributeMaxDynamicSharedMemorySize,
                         ATT_SMEM);

    // ---- preconvert all weights (once per replay, fully parallel)
    {
        int n;
        n = L_ * D_ * 3 * D_;  cvt_kernel<<<n / 1024, 256>>>(qkv_w, wqkv, n);
        n = L_ * D_ * D_;      cvt_kernel<<<n / 1024, 256>>>(out_w, wout, n);
        n = L_ * D_ * FF_;     cvt_kernel<<<n / 1024, 256>>>(fc1_w, wfc1, n);
        n = L_ * FF_ * D_;     cvt_kernel<<<n / 1024, 256>>>(fc2_w, wfc2, n);
        n = D_ * V_;           cvt_kernel<<<n / 1024, 256>>>(w_out, wlog, n);
    }

    embed_kernel<<<TOK_, 256>>>(tokens, emb, x, xh);

    for (int l = 0; l < L_; ++l) {
        // qkv = x @ qkv_w + b -> fp16 (mode 2) into hh
        mma_gemm<<<dim3(3072 / 256, TOK_ / 128), 512, GEMM_SMEM>>>(
            xh, wqkv + (size_t)l * D_ * 3 * D_, qkv_b + (size_t)l * 3 * D_,
            nullptr, hh, 3 * D_, D_, 2);
        // attention -> oh
        attn_mma<<<dim3(S_ / 64, B_ * H_), 128, ATT_SMEM>>>(hh, oh);
        // out proj -> tmp fp32
        mma_gemm<<<dim3(D_ / 256, TOK_ / 128), 512, GEMM_SMEM>>>(
            oh, wout + (size_t)l * D_ * D_, out_b + (size_t)l * D_,
            tmp, nullptr, D_, D_, 0);
        add_ln_kernel<<<TOK_, 256>>>(x, tmp, ln1_g + l * D_, ln1_b + l * D_, xh);
        // fc1 (relu, fp16)
        mma_gemm<<<dim3(FF_ / 256, TOK_ / 128), 512, GEMM_SMEM>>>(
            xh, wfc1 + (size_t)l * D_ * FF_, fc1_b + (size_t)l * FF_,
            nullptr, hh, FF_, D_, 1);
        // fc2
        mma_gemm<<<dim3(D_ / 256, TOK_ / 128), 512, GEMM_SMEM>>>(
            hh, wfc2 + (size_t)l * FF_ * D_, fc2_b + (size_t)l * D_,
            o, nullptr, D_, FF_, 0);
        add_ln_kernel<<<TOK_, 256>>>(x, o, ln2_g + l * D_, ln2_b + l * D_, xh);
    }

    // logits
    mma_gemm<<<dim3(V_ / 256, TOK_ / 128), 512, GEMM_SMEM>>>(
        xh, wlog, b_out, out, nullptr, V_, D_, 0);
}

// round 16
// speedup vs baseline: 1.0423x; 1.0055x over previous
#include <cuda_runtime.h>
#include <cuda_fp16.h>
#include <math.h>
#include <stdint.h>

#define B_ 2
#define S_ 2048
#define D_ 1024
#define L_ 6
#define H_ 16
#define HD_ 64
#define FF_ 4096
#define V_ 32000
#define TOK_ (B_ * S_)          // 4096 token rows

#define SCALE_LOG2 0.1803368801111f   // 0.125 * log2(e)

// ---------------- scratch (static device globals; no allocation) ----------
__device__ float g_x[TOK_ * D_];                 // fp32 residual stream
__device__ float g_tmp[TOK_ * FF_];              // out-proj / fc2 fp32 out
__device__ float g_o[TOK_ * D_];                 // fc2 out (pre-LN2)
__device__ __half g_xh[TOK_ * D_];               // x (fp16 plane)
__device__ __half g_oh[TOK_ * D_];               // attention out
__device__ __half g_hh[TOK_ * FF_];              // qkv / ffn hidden (fp16)
// preconverted fp16 weights, layout [K][N] per layer
__device__ __half g_wqkv[(size_t)L_ * D_ * 3 * D_];
__device__ __half g_wout[(size_t)L_ * D_ * D_];
__device__ __half g_wfc1[(size_t)L_ * D_ * FF_];
__device__ __half g_wfc2[(size_t)L_ * FF_ * D_];
__device__ __half g_wlog[(size_t)D_ * V_];

__device__ __forceinline__ uint32_t packh2(float x, float y) {
    __half2 t = __floats2half2_rn(x, y);
    return *reinterpret_cast<uint32_t*>(&t);
}

// ---------------- PTX helpers ----------------------------------------------
__device__ __forceinline__ uint32_t sptr(const void* p) {
    return (uint32_t)__cvta_generic_to_shared(p);
}
#define LDSM4(R0, R1, R2, R3, ADDR) \
    asm volatile("ldmatrix.sync.aligned.m8n8.x4.shared.b16 {%0,%1,%2,%3}, [%4];" \
                 : "=r"(R0), "=r"(R1), "=r"(R2), "=r"(R3) : "r"(ADDR))
#define LDSM4T(R0, R1, R2, R3, ADDR) \
    asm volatile("ldmatrix.sync.aligned.m8n8.x4.trans.shared.b16 {%0,%1,%2,%3}, [%4];" \
                 : "=r"(R0), "=r"(R1), "=r"(R2), "=r"(R3) : "r"(ADDR))
#define MMA16816(Cv, Ar, Bb0, Bb1) \
    asm volatile("mma.sync.aligned.m16n8k16.row.col.f32.f16.f16.f32 " \
                 "{%0,%1,%2,%3},{%4,%5,%6,%7},{%8,%9},{%0,%1,%2,%3};" \
                 : "+f"(Cv[0]), "+f"(Cv[1]), "+f"(Cv[2]), "+f"(Cv[3]) \
                 : "r"(Ar[0]), "r"(Ar[1]), "r"(Ar[2]), "r"(Ar[3]), \
                   "r"(Bb0), "r"(Bb1))
#define EX2X2(D, S) \
    asm volatile("ex2.approx.f16x2 %0, %1;" : "=r"(D) : "r"(S))
#define CP16(DST, SRC) \
    asm volatile("cp.async.cg.shared.global [%0], [%1], 16;" :: "r"(DST), "l"(SRC))
#define CPCOMMIT() asm volatile("cp.async.commit_group;")
#define CPWAIT1()  asm volatile("cp.async.wait_group 1;")
#define CPWAIT2()  asm volatile("cp.async.wait_group 2;")
#define CPWAITALL() asm volatile("cp.async.wait_all;")

#define HALF2_ONES 0x3C003C00u

// ---------------- weight convert: fp32 -> fp16 (same [K][N] layout) -------
__global__ void cvt_kernel(const float* __restrict__ in,
                           __half* __restrict__ hi, int n) {
    int i = (blockIdx.x * 256 + threadIdx.x) * 4;
    if (i >= n) return;
    float4 v = *(const float4*)(in + i);
    *(uint32_t*)(hi + i)     = packh2(v.x, v.y);
    *(uint32_t*)(hi + i + 2) = packh2(v.z, v.w);
}

// ---------------- embedding + positional encoding (+ fp16 out) ------------
__global__ void embed_kernel(const int* __restrict__ tokens,
                             const float* __restrict__ emb,
                             float* __restrict__ x,
                             __half* __restrict__ xh) {
    int row = blockIdx.x;
    int s   = row & (S_ - 1);
    int tok = tokens[row];
    const float* erow = emb + (size_t)tok * D_;
    size_t base = (size_t)row * D_;
    const float kfac = -0.00899447301950812f;   // -ln(10000)/1024
    #pragma unroll
    for (int j = 0; j < 4; ++j) {
        int c = threadIdx.x + j * 256;
        float freq = expf(kfac * (float)(c & ~1));
        float arg  = (float)s * freq;
        float pe   = (c & 1) ? cosf(arg) : sinf(arg);
        float v = erow[c] + pe;
        x[base + c] = v;
        xh[base + c] = __float2half_rn(v);
    }
}

// ===================== fp16 tensor-core GEMM (single-term) =================
// C = Ah[MxK] @ Bh[KxN] + bias, fp32 accum.
// 512 threads = 16 warps (4m x 4n), warp tile 32x64, block tile 128x256x64.
// 4-stage cp.async pipeline, one __syncthreads per k-chunk.
#define AST2 72
#define BST2 264
#define A_EL (128 * AST2)                 // 9216
#define B_EL2 (64 * BST2)                 // 16896
#define STG_E (A_EL + B_EL2)              // 26112 elems
#define GEMM_SMEM (4 * STG_E * 2)         // 208896 bytes

#define ISSUE_STAGE(SIDX, K0) do {                                           \
    __half* _b = sm + (SIDX) * STG_E;                                        \
    _Pragma("unroll")                                                        \
    for (int _i = 0; _i < 2; ++_i) {                                         \
        int _id = tid + _i * 512;                                            \
        int _r = _id >> 3, _c = (_id & 7) << 3;                              \
        CP16(sptr(_b + _r * AST2 + _c), gA + (size_t)_r * K + (K0) + _c);    \
    }                                                                        \
    _Pragma("unroll")                                                        \
    for (int _i = 0; _i < 4; ++_i) {                                         \
        int _id = tid + _i * 512;                                            \
        int _r = _id >> 5, _c = (_id & 31) << 3;                             \
        CP16(sptr(_b + A_EL + _r * BST2 + _c),                               \
             gB + (size_t)((K0) + _r) * N + _c);                             \
    }                                                                        \
} while (0)

// mode 0: fp32 C. mode 1: relu + fp16. mode 2: fp16 (no relu).
__global__ void __launch_bounds__(512, 1)
mma_gemm(const __half* __restrict__ Ah,
         const __half* __restrict__ Bh,
         const float* __restrict__ bias,
         float* __restrict__ C,
         __half* __restrict__ Ch,
         int N, int K, int mode) {
    extern __shared__ __half sm[];

    const int tid = threadIdx.x;
    const int wid = tid >> 5, lane = tid & 31;
    const int wm = (wid >> 2) << 5;     // 0..96
    const int wn = (wid & 3) << 6;      // 0..192
    const int bx = blockIdx.x, by = blockIdx.y;

    const __half* gA = Ah + (size_t)(by * 128) * K;
    const __half* gB = Bh + bx * 256;

    float acc[2][8][4];
    #pragma unroll
    for (int i = 0; i < 2; ++i)
        #pragma unroll
        for (int j = 0; j < 8; ++j)
            #pragma unroll
            for (int t = 0; t < 4; ++t) acc[i][j][t] = 0.f;

    ISSUE_STAGE(0, 0);   CPCOMMIT();
    ISSUE_STAGE(1, 64);  CPCOMMIT();
    ISSUE_STAGE(2, 128); CPCOMMIT();

    const int ntile = K >> 6;
    for (int it = 0; it < ntile; ++it) {
        CPWAIT2();
        __syncthreads();

        int nk = (it + 3) << 6;
        if (nk < K) {
            ISSUE_STAGE((it + 3) & 3, nk);
        }
        CPCOMMIT();

        const __half* ah = sm + (it & 3) * STG_E;
        const __half* bsh = ah + A_EL;

        #pragma unroll
        for (int kc = 0; kc < 4; ++kc) {
            uint32_t a_f[2][4];
            int af = lane & 15;
            int ac = kc * 16 + ((lane >> 4) << 3);
            #pragma unroll
            for (int mt = 0; mt < 2; ++mt) {
                uint32_t ad = sptr(ah + (wm + mt * 16 + af) * AST2 + ac);
                LDSM4(a_f[mt][0], a_f[mt][1], a_f[mt][2], a_f[mt][3], ad);
            }
            int bkr = kc * 16 + (lane & 15);
            #pragma unroll
            for (int p = 0; p < 4; ++p) {
                int bnc = wn + p * 16 + ((lane >> 4) << 3);
                uint32_t b0, b1, b2, b3;
                uint32_t bd = sptr(bsh + bkr * BST2 + bnc);
                LDSM4T(b0, b1, b2, b3, bd);
                MMA16816(acc[0][2*p],   a_f[0], b0, b1);
                MMA16816(acc[0][2*p+1], a_f[0], b2, b3);
                MMA16816(acc[1][2*p],   a_f[1], b0, b1);
                MMA16816(acc[1][2*p+1], a_f[1], b2, b3);
            }
        }
        // no trailing sync: stage (it&3) is rewritten only in iteration it+1,
        // after that iteration's top-of-loop __syncthreads.
    }

    #pragma unroll
    for (int mt = 0; mt < 2; ++mt) {
        int row = by * 128 + wm + mt * 16 + (lane >> 2);
        #pragma unroll
        for (int nt = 0; nt < 8; ++nt) {
            int col = bx * 256 + wn + nt * 8 + ((lane & 3) << 1);
            float2 bv = *(const float2*)(bias + col);
            float v0 = acc[mt][nt][0] + bv.x;
            float v1 = acc[mt][nt][1] + bv.y;
            float v2 = acc[mt][nt][2] + bv.x;
            float v3 = acc[mt][nt][3] + bv.y;
            if (mode == 0) {
                float2 o0 = {v0, v1}, o1 = {v2, v3};
                *(float2*)(C + (size_t)row * N + col)       = o0;
                *(float2*)(C + (size_t)(row + 8) * N + col) = o1;
            } else {
                if (mode == 1) {
                    v0 = fmaxf(v0, 0.f); v1 = fmaxf(v1, 0.f);
                    v2 = fmaxf(v2, 0.f); v3 = fmaxf(v3, 0.f);
                }
                *(uint32_t*)(Ch + (size_t)row * N + col)       = packh2(v0, v1);
                *(uint32_t*)(Ch + (size_t)(row + 8) * N + col) = packh2(v2, v3);
            }
        }
    }
}

// ===================== tensor-core causal flash attention ==================
// 128 threads (4 warps), 64 queries of one (b,h), 128-key tiles, double-buffered.
// log2-domain softmax: scale = 0.125*log2(e); P via ex2.approx.f16x2;
// denominator via extra MMA against all-ones B fragment (exact fp32).
#define APAD 72
#define AQBUF 4608                    // 64*72 (Q)
#define KVPL (128 * APAD)             // 9216 elems per K or V plane
#define AKV0 AQBUF                    // after Q
#define AKVSTRIDE (2 * KVPL)          // kh, vh per stage
#define ATT_SMEM ((AQBUF + 2 * AKVSTRIDE) * 2)   // 82944 bytes

__global__ void __launch_bounds__(128, 2)
attn_mma(const __half* __restrict__ qh,
         __half* __restrict__ oh) {
    extern __shared__ __half sm[];
    const int tid = threadIdx.x;
    const int wid = tid >> 5, lane = tid & 31;
    const int qb = gridDim.x - 1 - blockIdx.x;
    const int bh = blockIdx.y;
    const int h = bh & (H_ - 1), b = bh >> 4;
    const int wq0 = wid << 4;

    const size_t seqbase = (size_t)(b * S_) * 3072 + h * 64;

    // Q tile (64 rows)
    {
        #pragma unroll
        for (int i = 0; i < 4; ++i) {
            int id = tid + i * 128;
            int row = id >> 3, col = (id & 7) << 3;
            size_t src = seqbase + (size_t)(qb * 64 + row) * 3072 + col;
            CP16(sptr(sm + row * APAD + col), qh + src);
        }
        CPCOMMIT();
    }
    // KV stage: 128 keys (K plane + V plane)
    #define ISSUE_KV(STG, KT0) do {                                         \
        __half* _kb = sm + AKV0 + (STG) * AKVSTRIDE;                        \
        _Pragma("unroll")                                                   \
        for (int i = 0; i < 8; ++i) {                                       \
            int id = tid + i * 128;                                         \
            int row = id >> 3, col = (id & 7) << 3;                         \
            size_t src = seqbase + (size_t)((KT0) * 128 + row) * 3072 + col;\
            uint32_t dst = sptr(_kb + row * APAD + col);                    \
            CP16(dst,            qh + src + 1024);                          \
            CP16(dst + KVPL * 2, qh + src + 2048);                          \
        }                                                                   \
        CPCOMMIT();                                                         \
    } while (0)

    const int ntk = (qb >> 1) + 1;       // number of 128-key tiles
    ISSUE_KV(0, 0);
    ISSUE_KV(1, (ntk > 1 ? 1 : 0));

    CPWAIT2();
    __syncthreads();
    uint32_t qf[4][4];
    {
        int af = lane & 15;
        #pragma unroll
        for (int kc = 0; kc < 4; ++kc) {
            int ac = kc * 16 + ((lane >> 4) << 3);
            uint32_t ad = sptr(sm + (wq0 + af) * APAD + ac);
            LDSM4(qf[kc][0], qf[kc][1], qf[kc][2], qf[kc][3], ad);
        }
    }

    float Od[8][4];
    #pragma unroll
    for (int i = 0; i < 8; ++i)
        #pragma unroll
        for (int j = 0; j < 4; ++j) Od[i][j] = 0.f;
    float dacc[4] = {0.f, 0.f, 0.f, 0.f};       // denominator accumulator (MMA)
    float m_a = -1e30f, m_b = -1e30f;

    int buf = 0;
    for (int kt = 0; kt < ntk; ++kt) {
        CPWAIT1();
        __syncthreads();

        const __half* kh = sm + AKV0 + buf * AKVSTRIDE;
        const __half* vh = kh + KVPL;

        float sreg[16][4];
        #pragma unroll
        for (int i = 0; i < 16; ++i)
            #pragma unroll
            for (int j = 0; j < 4; ++j) sreg[i][j] = 0.f;

        // scores: 64 queries x 128 keys
        #pragma unroll
        for (int kc = 0; kc < 4; ++kc) {
            int krow = ((lane >> 4) << 3) + (lane & 7);
            int kcol = kc * 16 + (((lane >> 3) & 1) << 3);
            #pragma unroll
            for (int ng = 0; ng < 8; ++ng) {
                uint32_t bh0, bh1, bh2, bh3;
                uint32_t ad = sptr(kh + (ng * 16 + krow) * APAD + kcol);
                LDSM4(bh0, bh1, bh2, bh3, ad);
                MMA16816(sreg[2*ng],   qf[kc], bh0, bh1);
                MMA16816(sreg[2*ng+1], qf[kc], bh2, bh3);
            }
        }

        // scale to log2 domain + causal mask (final tile only)
        int ra = wq0 + (lane >> 2);
        int cb = (lane & 3) << 1;
        bool last = (kt == ntk - 1);
        #pragma unroll
        for (int nt = 0; nt < 16; ++nt) {
            #pragma unroll
            for (int j = 0; j < 4; ++j) {
                float s = sreg[nt][j] * SCALE_LOG2;
                if (last) {
                    int col = kt * 128 + nt * 8 + cb + (j & 1);
                    int row = qb * 64 + ra + ((j >> 1) << 3);
                    if (col > row) s = -1e30f;
                }
                sreg[nt][j] = s;
            }
        }
        // row max (log2 domain)
        float mxa = -1e30f, mxb = -1e30f;
        #pragma unroll
        for (int nt = 0; nt < 16; ++nt) {
            mxa = fmaxf(mxa, fmaxf(sreg[nt][0], sreg[nt][1]));
            mxb = fmaxf(mxb, fmaxf(sreg[nt][2], sreg[nt][3]));
        }
        mxa = fmaxf(mxa, __shfl_xor_sync(0xffffffffu, mxa, 1));
        mxa = fmaxf(mxa, __shfl_xor_sync(0xffffffffu, mxa, 2));
        mxb = fmaxf(mxb, __shfl_xor_sync(0xffffffffu, mxb, 1));
        mxb = fmaxf(mxb, __shfl_xor_sync(0xffffffffu, mxb, 2));
        float mna = fmaxf(m_a, mxa), mnb = fmaxf(m_b, mxb);
        float ca = exp2f(m_a - mna), cbr = exp2f(m_b - mnb);
        m_a = mna; m_b = mnb;
        #pragma unroll
        for (int nt = 0; nt < 8; ++nt) {
            Od[nt][0] *= ca;  Od[nt][1] *= ca;
            Od[nt][2] *= cbr; Od[nt][3] *= cbr;
        }
        dacc[0] *= ca;  dacc[1] *= ca;
        dacc[2] *= cbr; dacc[3] *= cbr;

        // P = 2^(s - m) directly as fp16 pairs; denominator via ones-MMA;
        // O += P @ Vh  (8 k-chunks of 16 keys)
        #pragma unroll
        for (int kc2 = 0; kc2 < 8; ++kc2) {
            uint32_t ph[4];
            uint32_t t0 = packh2(sreg[2*kc2][0]   - mna, sreg[2*kc2][1]   - mna);
            uint32_t t1 = packh2(sreg[2*kc2][2]   - mnb, sreg[2*kc2][3]   - mnb);
            uint32_t t2 = packh2(sreg[2*kc2+1][0] - mna, sreg[2*kc2+1][1] - mna);
            uint32_t t3 = packh2(sreg[2*kc2+1][2] - mnb, sreg[2*kc2+1][3] - mnb);
            EX2X2(ph[0], t0);
            EX2X2(ph[1], t1);
            EX2X2(ph[2], t2);
            EX2X2(ph[3], t3);
            MMA16816(dacc, ph, HALF2_ONES, HALF2_ONES);
            int vr = kc2 * 16 + (lane & 15);
            #pragma unroll
            for (int ng = 0; ng < 4; ++ng) {
                int vc = ng * 16 + ((lane >> 4) << 3);
                uint32_t v0, v1, v2, v3;
                uint32_t ad = sptr(vh + vr * APAD + vc);
                LDSM4T(v0, v1, v2, v3, ad);
                MMA16816(Od[2*ng],   ph, v0, v1);
                MMA16816(Od[2*ng+1], ph, v2, v3);
            }
        }
        __syncthreads();
        if (kt + 2 < ntk) ISSUE_KV(buf, kt + 2);
        CPCOMMIT();
        buf ^= 1;
    }

    CPWAITALL();

    // all n-columns of the ones-MMA result are identical -> dacc[0]/dacc[2]
    // hold the row sums for rows ra and ra+8 in every thread of the quad.
    float inva = 1.f / dacc[0], invb = 1.f / dacc[2];
    int gq_a = qb * 64 + wq0 + (lane >> 2);
    size_t oa = (size_t)(b * S_ + gq_a) * D_ + h * 64 + ((lane & 3) << 1);
    size_t ob = oa + (size_t)8 * D_;
    #pragma unroll
    for (int nt = 0; nt < 8; ++nt) {
        *(uint32_t*)(oh + oa + nt * 8) = packh2(Od[nt][0] * inva, Od[nt][1] * inva);
        *(uint32_t*)(oh + ob + nt * 8) = packh2(Od[nt][2] * invb, Od[nt][3] * invb);
    }
}

// ---------------- fused residual add + LayerNorm (single-pass reduce) -----
__global__ void add_ln_kernel(float* __restrict__ x,
                              const float* __restrict__ r,
                              const float* __restrict__ g,
                              const float* __restrict__ bb,
                              __half* __restrict__ xh) {
    int row = blockIdx.x;
    int tid = threadIdx.x;
    size_t base = (size_t)row * D_;
    float v[4];
    float s = 0.f, sq = 0.f;
    #pragma unroll
    for (int j = 0; j < 4; ++j) {
        int c = tid + j * 256;
        v[j] = x[base + c] + r[base + c];
        s += v[j];
        sq = fmaf(v[j], v[j], sq);
    }
    __shared__ float sh_s[8], sh_q[8];
    #pragma unroll
    for (int off = 16; off > 0; off >>= 1) {
        s  += __shfl_xor_sync(0xffffffffu, s, off);
        sq += __shfl_xor_sync(0xffffffffu, sq, off);
    }
    if ((tid & 31) == 0) { sh_s[tid >> 5] = s; sh_q[tid >> 5] = sq; }
    __syncthreads();
    if (tid < 32) {
        float t  = (tid < 8) ? sh_s[tid] : 0.f;
        float tq = (tid < 8) ? sh_q[tid] : 0.f;
        #pragma unroll
        for (int off = 4; off > 0; off >>= 1) {
            t  += __shfl_xor_sync(0xffffffffu, t, off);
            tq += __shfl_xor_sync(0xffffffffu, tq, off);
        }
        if (tid == 0) { sh_s[0] = t; sh_q[0] = tq; }
    }
    __syncthreads();
    float mu  = sh_s[0] * (1.f / 1024.f);
    float var = sh_q[0] * (1.f / 1024.f) - mu * mu;
    float rstd = rsqrtf(var + 1e-5f);
    #pragma unroll
    for (int j = 0; j < 4; ++j) {
        int c = tid + j * 256;
        float y = (v[j] - mu) * rstd * g[c] + bb[c];
        x[base + c] = y;
        xh[base + c] = __float2half_rn(y);
    }
}

// ---------------------------------------------------------------------------
extern "C" void kernel_launch(void* const* d_in, const int* in_sizes, int n_in,
                              void* d_out, int out_size) {
    const int*   tokens = (const int*)  d_in[0];
    const float* emb    = (const float*)d_in[1];
    const float* qkv_w  = (const float*)d_in[2];
    const float* qkv_b  = (const float*)d_in[3];
    const float* out_w  = (const float*)d_in[4];
    const float* out_b  = (const float*)d_in[5];
    const float* fc1_w  = (const float*)d_in[6];
    const float* fc1_b  = (const float*)d_in[7];
    const float* fc2_w  = (const float*)d_in[8];
    const float* fc2_b  = (const float*)d_in[9];
    const float* ln1_g  = (const float*)d_in[10];
    const float* ln1_b  = (const float*)d_in[11];
    const float* ln2_g  = (const float*)d_in[12];
    const float* ln2_b  = (const float*)d_in[13];
    const float* w_out  = (const float*)d_in[14];
    const float* b_out  = (const float*)d_in[15];
    float* out = (float*)d_out;

    float *x, *tmp, *o;
    __half *xh, *oh, *hh, *wqkv, *wout, *wfc1, *wfc2, *wlog;
    cudaGetSymbolAddress((void**)&x,    g_x);
    cudaGetSymbolAddress((void**)&tmp,  g_tmp);
    cudaGetSymbolAddress((void**)&o,    g_o);
    cudaGetSymbolAddress((void**)&xh,   g_xh);
    cudaGetSymbolAddress((void**)&oh,   g_oh);
    cudaGetSymbolAddress((void**)&hh,   g_hh);
    cudaGetSymbolAddress((void**)&wqkv, g_wqkv);
    cudaGetSymbolAddress((void**)&wout, g_wout);
    cudaGetSymbolAddress((void**)&wfc1, g_wfc1);
    cudaGetSymbolAddress((void**)&wfc2, g_wfc2);
    cudaGetSymbolAddress((void**)&wlog, g_wlog);

    cudaFuncSetAttribute(mma_gemm, cudaFuncAttributeMaxDynamicSharedMemorySize,
                         GEMM_SMEM);
    cudaFuncSetAttribute(attn_mma, cudaFuncAttributeMaxDynamicSharedMemorySize,
                         ATT_SMEM);

    // ---- preconvert all weights (once per replay, fully parallel)
    {
        int n;
        n = L_ * D_ * 3 * D_;  cvt_kernel<<<n / 1024, 256>>>(qkv_w, wqkv, n);
        n = L_ * D_ * D_;      cvt_kernel<<<n / 1024, 256>>>(out_w, wout, n);
        n = L_ * D_ * FF_;     cvt_kernel<<<n / 1024, 256>>>(fc1_w, wfc1, n);
        n = L_ * FF_ * D_;     cvt_kernel<<<n / 1024, 256>>>(fc2_w, wfc2, n);
        n = D_ * V_;           cvt_kernel<<<n / 1024, 256>>>(w_out, wlog, n);
    }

    embed_kernel<<<TOK_, 256>>>(tokens, emb, x, xh);

    for (int l = 0; l < L_; ++l) {
        // qkv = x @ qkv_w + b -> fp16 (mode 2) into hh
        mma_gemm<<<dim3(3072 / 256, TOK_ / 128), 512, GEMM_SMEM>>>(
            xh, wqkv + (size_t)l * D_ * 3 * D_, qkv_b + (size_t)l * 3 * D_,
            nullptr, hh, 3 * D_, D_, 2);
        // attention -> oh
        attn_mma<<<dim3(S_ / 64, B_ * H_), 128, ATT_SMEM>>>(hh, oh);
        // out proj -> tmp fp32
        mma_gemm<<<dim3(D_ / 256, TOK_ / 128), 512, GEMM_SMEM>>>(
            oh, wout + (size_t)l * D_ * D_, out_b + (size_t)l * D_,
            tmp, nullptr, D_, D_, 0);
        add_ln_kernel<<<TOK_, 256>>>(x, tmp, ln1_g + l * D_, ln1_b + l * D_, xh);
        // fc1 (relu, fp16)
        mma_gemm<<<dim3(FF_ / 256, TOK_ / 128), 512, GEMM_SMEM>>>(
            xh, wfc1 + (size_t)l * D_ * FF_, fc1_b + (size_t)l * FF_,
            nullptr, hh, FF_, D_, 1);
        // fc2
        mma_gemm<<<dim3(D_ / 256, TOK_ / 128), 512, GEMM_SMEM>>>(
            hh, wfc2 + (size_t)l * FF_ * D_, fc2_b + (size_t)l * D_,
            o, nullptr, D_, FF_, 0);
        add_ln_kernel<<<TOK_, 256>>>(x, o, ln2_g + l * D_, ln2_b + l * D_, xh);
    }

    // logits
    mma_gemm<<<dim3(V_ / 256, TOK_ / 128), 512, GEMM_SMEM>>>(
        xh, wlog, b_out, out, nullptr, V_, D_, 0);
}